// round 3
// baseline (speedup 1.0000x reference)
#include <cuda_runtime.h>

#define BB   2
#define NN   512
#define OBJ  320
#define GEO  6
#define LANG 256
#define HID  256
#define ROWS (BB*NN)   // 1024
#define TI2  8
#define TI4  8
#define CJ   16

#define C2 0.3989423f
#define C4 -0.0664904f
#define TWO_C2 0.79788456f

typedef unsigned long long u64;

__device__ __forceinline__ u64 pk2(float lo, float hi) {
    u64 r; asm("mov.b64 %0, {%1, %2};" : "=l"(r) : "f"(lo), "f"(hi)); return r;
}
__device__ __forceinline__ void upk2(float& lo, float& hi, u64 v) {
    asm("mov.b64 {%0, %1}, %2;" : "=f"(lo), "=f"(hi) : "l"(v));
}
__device__ __forceinline__ u64 ffma2(u64 a, u64 b, u64 c) {
    u64 d; asm("fma.rn.f32x2 %0, %1, %2, %3;" : "=l"(d) : "l"(a), "l"(b), "l"(c)); return d;
}

// L2-resident scratch
__device__ float g_emb[ROWS*OBJ];    // normalized embeddings
__device__ float g_hl [BB*HID];      // lang_n@Wl + b1
__device__ float g_FAt[HID*ROWS];    // [k][i]: 2*c2*W2[k]*hi[i,k]
__device__ float g_FBt[HID*ROWS];    // [k][j]: hj[j,k]
__device__ float g_Si [ROWS];
__device__ float g_Sj [ROWS];
__device__ float g_sc [ROWS*NN];     // cross scores (pre Si/Sj)

// ---------------- K0: normalize utterance, hl = lang_n@Wl + b1 ----------------
__global__ void __launch_bounds__(512) k_lang(const float* __restrict__ utter,
                                              const float* __restrict__ W1,
                                              const float* __restrict__ b1) {
    int b = blockIdx.x, t = threadIdx.x;   // 512 threads
    int h = t & 255, half = t >> 8;
    __shared__ float ls[LANG];
    __shared__ float red[8];
    __shared__ float part[2][HID];
    float v = 0.f;
    if (half == 0) {
        v = utter[b*LANG + t];
        float ss = v*v;
        #pragma unroll
        for (int o = 16; o; o >>= 1) ss += __shfl_xor_sync(0xffffffffu, ss, o);
        if ((t & 31) == 0) red[t >> 5] = ss;
    }
    __syncthreads();
    if (half == 0) {
        float tot = 0.f;
        #pragma unroll
        for (int w = 0; w < 8; w++) tot += red[w];
        ls[t] = v * rsqrtf(tot);
    }
    __syncthreads();
    float acc = (half == 0) ? b1[h] : 0.f;
    const float* Wl = W1 + (2*OBJ + GEO)*HID + h;
    int l0 = half * 128;
    #pragma unroll 4
    for (int l = 0; l < 128; l++) acc = fmaf(ls[l0 + l], Wl[(l0 + l)*HID], acc);
    part[half][h] = acc;
    __syncthreads();
    if (half == 0) g_hl[b*HID + h] = part[0][h] + part[1][h];
}

// ---------------- K1: normalize + projections + features + Si/Sj (f32x2) ----------------
__global__ void __launch_bounds__(256) k_proj(const float* __restrict__ emb_raw,
                                              const float* __restrict__ geom,
                                              const float* __restrict__ W1,
                                              const float* __restrict__ W2) {
    __shared__ float  e_s[TI2][OBJ];    // 10 KB
    __shared__ float2 ep [OBJ][4];      // 10 KB row-pairs
    __shared__ float2 gp [GEO][4];
    __shared__ float  red_si[8][8], red_sj[8][8];
    int row0 = blockIdx.x * TI2;
    int t = threadIdx.x;                // h = t
    int lane = t & 31, warp = t >> 5;

    for (int idx = t; idx < TI2*OBJ; idx += 256)
        ((float*)e_s)[idx] = emb_raw[row0*OBJ + idx];
    __syncthreads();

    // normalize: warp w owns row w; also persist to g_emb
    {
        float ss = 0.f;
        for (int d = lane; d < OBJ; d += 32) { float v = e_s[warp][d]; ss = fmaf(v, v, ss); }
        #pragma unroll
        for (int o = 16; o; o >>= 1) ss += __shfl_xor_sync(0xffffffffu, ss, o);
        float inv = rsqrtf(ss);
        float* gdst = g_emb + (row0 + warp)*OBJ;
        for (int d = lane; d < OBJ; d += 32) {
            float v = e_s[warp][d] * inv;
            e_s[warp][d] = v;
            gdst[d] = v;
        }
    }
    __syncthreads();

    // build row-pair layout
    for (int idx = t; idx < OBJ*4; idx += 256) {
        int d = idx >> 2, p = idx & 3;
        ep[d][p] = make_float2(e_s[2*p][d], e_s[2*p+1][d]);
    }
    if (t < GEO*4) {
        int d = t >> 2, p = t & 3;
        gp[d][p] = make_float2(geom[(row0 + 2*p)*GEO + d], geom[(row0 + 2*p + 1)*GEO + d]);
    }
    __syncthreads();

    u64 ai[4], aj[4];
    #pragma unroll
    for (int p = 0; p < 4; p++) { ai[p] = 0ull; aj[p] = 0ull; }
    const float* Wi = W1 + t;
    const float* Wj = W1 + OBJ*HID + t;
    #pragma unroll 4
    for (int d = 0; d < OBJ; d++) {
        float wi = Wi[d*HID];
        float wj = Wj[d*HID];
        u64 wip = pk2(wi, wi), wjp = pk2(wj, wj);
        #pragma unroll
        for (int p = 0; p < 4; p++) {
            u64 e2 = *(const u64*)&ep[d][p];
            ai[p] = ffma2(e2, wip, ai[p]);
            aj[p] = ffma2(e2, wjp, aj[p]);
        }
    }
    const float* Wg = W1 + 2*OBJ*HID + t;
    #pragma unroll
    for (int g = 0; g < GEO; g++) {
        float wg = Wg[g*HID];
        u64 wgp = pk2(wg, wg), wgm = pk2(-wg, -wg);
        #pragma unroll
        for (int p = 0; p < 4; p++) {
            u64 g2 = *(const u64*)&gp[g][p];
            ai[p] = ffma2(g2, wgm, ai[p]);
            aj[p] = ffma2(g2, wgp, aj[p]);
        }
    }

    float w2v = W2[t];
    float hlv = g_hl[(row0 >> 9)*HID + t];
    float sir[8], sjr[8];
    #pragma unroll
    for (int p = 0; p < 4; p++) {
        float a0, a1, j0v, j1v;
        upk2(a0, a1, ai[p]);
        upk2(j0v, j1v, aj[p]);
        float h0 = a0 + hlv, h1 = a1 + hlv;
        *(float2*)&g_FAt[t*ROWS + row0 + 2*p] =
            make_float2(TWO_C2*w2v*h0, TWO_C2*w2v*h1);
        *(float2*)&g_FBt[t*ROWS + row0 + 2*p] = make_float2(j0v, j1v);
        float u0 = h0*h0, u1 = h1*h1;
        sir[2*p]   = w2v * fmaf(u0, fmaf(C4, u0, C2), 0.5f*h0);
        sir[2*p+1] = w2v * fmaf(u1, fmaf(C4, u1, C2), 0.5f*h1);
        float v0 = j0v*j0v, v1 = j1v*j1v;
        sjr[2*p]   = w2v * fmaf(v0, fmaf(C4, v0, C2), 0.5f*j0v);
        sjr[2*p+1] = w2v * fmaf(v1, fmaf(C4, v1, C2), 0.5f*j1v);
    }
    #pragma unroll
    for (int r = 0; r < 8; r++) {
        float si = sir[r], sj = sjr[r];
        #pragma unroll
        for (int o = 16; o; o >>= 1) {
            si += __shfl_xor_sync(0xffffffffu, si, o);
            sj += __shfl_xor_sync(0xffffffffu, sj, o);
        }
        if (lane == 0) { red_si[warp][r] = si; red_sj[warp][r] = sj; }
    }
    __syncthreads();
    if (t < 64) {
        int r = t >> 3, w = t & 7;
        float v = red_si[w][r];
        #pragma unroll
        for (int o = 4; o; o >>= 1) v += __shfl_xor_sync(0xffffffffu, v, o, 8);
        if ((t & 7) == 0) g_Si[row0 + r] = v;
    } else if (t < 128) {
        int tt = t - 64;
        int r = tt >> 3, w = tt & 7;
        float v = red_sj[w][r];
        #pragma unroll
        for (int o = 4; o; o >>= 1) v += __shfl_xor_sync(0xffffffffu, v, o, 8);
        if ((tt & 7) == 0) g_Sj[row0 + r] = v;
    }
}

// ---------------- K2: cross GEMM with f32x2 (64x64 tile, K=256) ----------------
__global__ void __launch_bounds__(256) k_gemm() {
    __shared__ float2 Asp[16][64];     // duplicated (a,a) pairs, 8 KB
    __shared__ float  Bs [16][64];     // 4 KB
    int t = threadIdx.x;
    int tx = t & 15, ty = t >> 4;
    int lk = t >> 4, l4 = (t & 15) * 4;
    int b  = blockIdx.z;
    int i0 = b*NN + blockIdx.y*64;
    int j0 = b*NN + blockIdx.x*64;

    const float* pa = g_FAt + lk*ROWS + i0 + l4;
    const float* pb = g_FBt + lk*ROWS + j0 + l4;

    u64 acc2[4][2];
    #pragma unroll
    for (int r = 0; r < 4; r++) { acc2[r][0] = 0ull; acc2[r][1] = 0ull; }

    float4 a4 = *(const float4*)pa;
    float4 b4 = *(const float4*)pb;

    #pragma unroll 1
    for (int ch = 0; ch < 16; ch++) {
        *(float4*)&Asp[lk][l4]     = make_float4(a4.x, a4.x, a4.y, a4.y);
        *(float4*)&Asp[lk][l4 + 2] = make_float4(a4.z, a4.z, a4.w, a4.w);
        *(float4*)&Bs[lk][l4] = b4;
        __syncthreads();
        if (ch < 15) {
            a4 = *(const float4*)(pa + (ch+1)*16*ROWS);
            b4 = *(const float4*)(pb + (ch+1)*16*ROWS);
        }
        #pragma unroll
        for (int k = 0; k < 16; k++) {
            ulonglong2 aA = *(const ulonglong2*)&Asp[k][ty*4];
            ulonglong2 aB = *(const ulonglong2*)&Asp[k][ty*4 + 2];
            ulonglong2 bP = *(const ulonglong2*)&Bs[k][tx*4];
            acc2[0][0] = ffma2(aA.x, bP.x, acc2[0][0]);
            acc2[0][1] = ffma2(aA.x, bP.y, acc2[0][1]);
            acc2[1][0] = ffma2(aA.y, bP.x, acc2[1][0]);
            acc2[1][1] = ffma2(aA.y, bP.y, acc2[1][1]);
            acc2[2][0] = ffma2(aB.x, bP.x, acc2[2][0]);
            acc2[2][1] = ffma2(aB.x, bP.y, acc2[2][1]);
            acc2[3][0] = ffma2(aB.y, bP.x, acc2[3][0]);
            acc2[3][1] = ffma2(aB.y, bP.y, acc2[3][1]);
        }
        __syncthreads();
    }

    int irow = i0 + ty*4;
    int jcol = blockIdx.x*64 + tx*4;
    #pragma unroll
    for (int r = 0; r < 4; r++) {
        float c0, c1, c2v, c3;
        upk2(c0, c1, acc2[r][0]);
        upk2(c2v, c3, acc2[r][1]);
        *(float4*)&g_sc[(irow + r)*NN + jcol] = make_float4(c0, c1, c2v, c3);
    }
}

// ---------------- K3: fused softmax + relation_scores + context GEMM ----------------
__global__ void __launch_bounds__(320) k_sctx(const float* __restrict__ b2p,
                                              float* __restrict__ out_scores,
                                              float* __restrict__ out_ctx) {
    __shared__ float  pw_s[TI4][NN];     // 16 KB
    __shared__ float4 e_s[CJ * 80];      // 20 KB
    int t = threadIdx.x;                 // 320 threads
    int lane = t & 31, warp = t >> 5;    // 10 warps
    int row0 = blockIdx.x * TI4;
    int b = row0 >> 9;

    // Phase A: softmax per row (one warp per row; full row inside one warp)
    if (warp < TI4) {
        int row = row0 + warp;
        const float4* scp = (const float4*)&g_sc[row*NN];
        const float4* sjp = (const float4*)&g_Sj[b*NN];
        float4 s[4];
        #pragma unroll
        for (int k = 0; k < 4; k++) {
            float4 c = scp[lane + k*32];
            float4 j = sjp[lane + k*32];
            s[k] = make_float4(c.x + j.x, c.y + j.y, c.z + j.z, c.w + j.w);
        }
        float m = -1e30f;
        #pragma unroll
        for (int k = 0; k < 4; k++)
            m = fmaxf(m, fmaxf(fmaxf(s[k].x, s[k].y), fmaxf(s[k].z, s[k].w)));
        #pragma unroll
        for (int o = 16; o; o >>= 1) m = fmaxf(m, __shfl_xor_sync(0xffffffffu, m, o));
        float se = 0.f, ses = 0.f;
        float4 e[4];
        #pragma unroll
        for (int k = 0; k < 4; k++) {
            e[k].x = __expf(s[k].x - m); e[k].y = __expf(s[k].y - m);
            e[k].z = __expf(s[k].z - m); e[k].w = __expf(s[k].w - m);
            se  += (e[k].x + e[k].y) + (e[k].z + e[k].w);
            ses = fmaf(e[k].x, s[k].x, fmaf(e[k].y, s[k].y,
                   fmaf(e[k].z, s[k].z, fmaf(e[k].w, s[k].w, ses))));
        }
        #pragma unroll
        for (int o = 16; o; o >>= 1) {
            se  += __shfl_xor_sync(0xffffffffu, se,  o);
            ses += __shfl_xor_sync(0xffffffffu, ses, o);
        }
        float inv = __fdividef(1.f, se);
        float4* pwp = (float4*)&pw_s[warp][0];
        #pragma unroll
        for (int k = 0; k < 4; k++)
            pwp[lane + k*32] = make_float4(e[k].x*inv, e[k].y*inv, e[k].z*inv, e[k].w*inv);
        if (lane == 0) out_scores[row] = ses*inv + g_Si[row] + b2p[0];
    }
    __syncthreads();

    // Phase B: context GEMM (f32x2 over d-pairs)
    int q = t % 80, y = t / 80;          // y in 0..3
    int r0 = y*2, r1 = y*2 + 1;
    u64 a0x = 0ull, a0y = 0ull, a1x = 0ull, a1y = 0ull;
    const float4* ebase = (const float4*)(g_emb + (size_t)b*NN*OBJ);

    for (int j0 = 0; j0 < NN; j0 += CJ) {
        #pragma unroll
        for (int k = 0; k < 4; k++) {
            int idx = t + k*320;
            e_s[idx] = ebase[j0*80 + idx];
        }
        __syncthreads();
        #pragma unroll
        for (int jj = 0; jj < CJ; jj++) {
            ulonglong2 e2 = *(const ulonglong2*)&e_s[jj*80 + q];
            float w0 = pw_s[r0][j0 + jj];
            float w1 = pw_s[r1][j0 + jj];
            u64 w0p = pk2(w0, w0);
            u64 w1p = pk2(w1, w1);
            a0x = ffma2(e2.x, w0p, a0x);
            a0y = ffma2(e2.y, w0p, a0y);
            a1x = ffma2(e2.x, w1p, a1x);
            a1y = ffma2(e2.y, w1p, a1y);
        }
        __syncthreads();
    }
    float x0, x1, x2, x3;
    float4* o4 = (float4*)out_ctx;
    upk2(x0, x1, a0x); upk2(x2, x3, a0y);
    o4[(row0 + r0)*80 + q] = make_float4(x0, x1, x2, x3);
    upk2(x0, x1, a1x); upk2(x2, x3, a1y);
    o4[(row0 + r1)*80 + q] = make_float4(x0, x1, x2, x3);
}

extern "C" void kernel_launch(void* const* d_in, const int* in_sizes, int n_in,
                              void* d_out, int out_size) {
    (void)in_sizes; (void)n_in; (void)out_size;
    const float* emb   = (const float*)d_in[0];
    const float* geom  = (const float*)d_in[1];
    const float* utter = (const float*)d_in[2];
    const float* W1    = (const float*)d_in[3];
    const float* b1    = (const float*)d_in[4];
    const float* W2    = (const float*)d_in[5];
    const float* b2    = (const float*)d_in[6];
    float* out = (float*)d_out;            // [0,1024): relation_scores; then context

    k_lang<<<BB, 512>>>(utter, W1, b1);
    k_proj<<<ROWS/TI2, 256>>>(emb, geom, W1, W2);
    {
        dim3 g(NN/64, NN/64, BB);
        k_gemm<<<g, 256>>>();
    }
    k_sctx<<<ROWS/TI4, 320>>>(b2, out, out + ROWS);
}